// round 9
// baseline (speedup 1.0000x reference)
#include <cuda_runtime.h>
#include <cuda_bf16.h>
#include <cstdint>
#include <math.h>

// Problem constants
#define BB 4
#define SS 2048
#define DD 1024
#define HH 16
#define HD 64
#define MTOT (BB*SS)      // 8192
#define NQKV (3*DD)       // 3072
#define NHEADS (BB*HH)    // 64

// Q pre-scale: 1/sqrt(64) * log2(e)  (softmax done in exp2 domain)
#define QSCALE 0.1803368801111204f

// ---------------------------------------------------------------------------
// Scratch (static device globals — allowed)
// ---------------------------------------------------------------------------
__device__ __nv_bfloat16 g_Xh[(size_t)MTOT*DD];
__device__ __nv_bfloat16 g_Xl[(size_t)MTOT*DD];
__device__ __nv_bfloat16 g_WqTh[(size_t)NQKV*DD];
__device__ __nv_bfloat16 g_WqTl[(size_t)NQKV*DD];
__device__ __nv_bfloat16 g_WoTh[(size_t)DD*DD];
__device__ __nv_bfloat16 g_WoTl[(size_t)DD*DD];
__device__ __nv_bfloat16 g_Qh[(size_t)NHEADS*SS*HD];
__device__ __nv_bfloat16 g_Ql[(size_t)NHEADS*SS*HD];
__device__ __nv_bfloat16 g_Kh[(size_t)NHEADS*SS*HD];
__device__ __nv_bfloat16 g_Kl[(size_t)NHEADS*SS*HD];
__device__ __nv_bfloat16 g_Vh[(size_t)NHEADS*SS*HD];
__device__ __nv_bfloat16 g_Vl[(size_t)NHEADS*SS*HD];
__device__ __nv_bfloat16 g_Oh[(size_t)MTOT*DD];
__device__ __nv_bfloat16 g_Ol[(size_t)MTOT*DD];

// ---------------------------------------------------------------------------
// PTX helpers (plain compute_103-compatible: mma.sync / ldmatrix / cp.async)
// ---------------------------------------------------------------------------
__device__ __forceinline__ uint32_t smem_u32(const void* p) {
    uint32_t a;
    asm("{ .reg .u64 t; cvta.to.shared.u64 t, %1; cvt.u32.u64 %0, t; }"
        : "=r"(a) : "l"(p));
    return a;
}
__device__ __forceinline__ void cp16(uint32_t dst, const void* src) {
    asm volatile("cp.async.cg.shared.global [%0], [%1], 16;\n"
                 :: "r"(dst), "l"(src));
}
#define CP_COMMIT() asm volatile("cp.async.commit_group;\n" ::: "memory")
#define CP_WAIT(n)  asm volatile("cp.async.wait_group %0;\n" :: "n"(n) : "memory")

__device__ __forceinline__ void ldsm4(uint32_t* r, uint32_t addr) {
    asm volatile("ldmatrix.sync.aligned.m8n8.x4.shared.b16 {%0,%1,%2,%3}, [%4];\n"
                 : "=r"(r[0]), "=r"(r[1]), "=r"(r[2]), "=r"(r[3]) : "r"(addr));
}
__device__ __forceinline__ void ldsm4t(uint32_t* r, uint32_t addr) {
    asm volatile("ldmatrix.sync.aligned.m8n8.x4.trans.shared.b16 {%0,%1,%2,%3}, [%4];\n"
                 : "=r"(r[0]), "=r"(r[1]), "=r"(r[2]), "=r"(r[3]) : "r"(addr));
}
__device__ __forceinline__ void mma_bf16(float* c, const uint32_t* a,
                                         uint32_t b0, uint32_t b1) {
    asm volatile(
        "mma.sync.aligned.m16n8k16.row.col.f32.bf16.bf16.f32 "
        "{%0,%1,%2,%3}, {%4,%5,%6,%7}, {%8,%9}, {%0,%1,%2,%3};\n"
        : "+f"(c[0]), "+f"(c[1]), "+f"(c[2]), "+f"(c[3])
        : "r"(a[0]), "r"(a[1]), "r"(a[2]), "r"(a[3]), "r"(b0), "r"(b1));
}
__device__ __forceinline__ float ex2(float x) {
    float y;
    asm("ex2.approx.ftz.f32 %0, %1;" : "=f"(y) : "f"(x));
    return y;
}
__device__ __forceinline__ void split2(float x, float y,
                                       __nv_bfloat162& h2, __nv_bfloat162& l2) {
    __nv_bfloat16 hx = __float2bfloat16(x);
    __nv_bfloat16 hy = __float2bfloat16(y);
    h2.x = hx; h2.y = hy;
    l2.x = __float2bfloat16(x - __bfloat162float(hx));
    l2.y = __float2bfloat16(y - __bfloat162float(hy));
}

// ---------------------------------------------------------------------------
// Fused prep: one launch.
//   blocks [0, 8192)              : split x -> g_Xh/g_Xl
//   blocks [8192, 8192+3072)      : transpose+split Wqkv -> g_WqT{h,l}
//   blocks [8192+3072, +1024)     : transpose+split Wo   -> g_WoT{h,l}
// ---------------------------------------------------------------------------
__device__ __forceinline__ void do_transpose_split(
    const float* __restrict__ W, int K, int N, int bx, int by, int tid,
    __nv_bfloat16* __restrict__ Th, __nv_bfloat16* __restrict__ Tl)
{
    __shared__ float t[32][33];
    int nb = bx * 32, kb = by * 32;
    int tx = tid & 31, ty = tid >> 5;
    #pragma unroll
    for (int j = 0; j < 4; j++)
        t[ty + j*8][tx] = W[(size_t)(kb + ty + j*8) * N + nb + tx];
    __syncthreads();
    #pragma unroll
    for (int j = 0; j < 4; j++) {
        int n = nb + ty + j*8;
        float v = t[tx][ty + j*8];
        __nv_bfloat16 h = __float2bfloat16(v);
        Th[(size_t)n * K + kb + tx] = h;
        Tl[(size_t)n * K + kb + tx] = __float2bfloat16(v - __bfloat162float(h));
    }
}

__global__ void __launch_bounds__(256) prep_kernel(
    const float* __restrict__ x, const float* __restrict__ Wqkv,
    const float* __restrict__ Wo)
{
    int bid = blockIdx.x;
    int tid = threadIdx.x;
    if (bid < 8192) {
        size_t i4 = ((size_t)bid * 256 + tid) * 4;
        float4 v = *(const float4*)(x + i4);
        __nv_bfloat162 h0, l0, h1, l1;
        split2(v.x, v.y, h0, l0);
        split2(v.z, v.w, h1, l1);
        *(__nv_bfloat162*)(g_Xh + i4)     = h0;
        *(__nv_bfloat162*)(g_Xh + i4 + 2) = h1;
        *(__nv_bfloat162*)(g_Xl + i4)     = l0;
        *(__nv_bfloat162*)(g_Xl + i4 + 2) = l1;
    } else if (bid < 8192 + 3072) {
        int b = bid - 8192;                 // 96 x 32 grid (nb x kb)
        do_transpose_split(Wqkv, DD, NQKV, b % 96, b / 96, tid, g_WqTh, g_WqTl);
    } else {
        int b = bid - 8192 - 3072;          // 32 x 32 grid
        do_transpose_split(Wo, DD, DD, b % 32, b / 32, tid, g_WoTh, g_WoTl);
    }
}

// ---------------------------------------------------------------------------
// Extended-K bf16 GEMM (3-pass split as K=3072) — unchanged from R6/R8 best.
// BM=BN=128, BK=64/stage, 256 threads, 8 warps (2m x 4n), 3-stage, 2 CTAs/SM.
// ---------------------------------------------------------------------------
#define GPITCH 144
#define GSTG (128*GPITCH)   // 18432 per operand per stage
#define SMEM_GEMM (6*GSTG)  // 110592

__global__ void __launch_bounds__(256, 2) gemm_ext_kernel(
    const __nv_bfloat16* __restrict__ Ah, const __nv_bfloat16* __restrict__ Al,
    const __nv_bfloat16* __restrict__ Bh, const __nv_bfloat16* __restrict__ Bl,
    const float* __restrict__ bias, float* __restrict__ out, int mode)
{
    extern __shared__ char sm[];
    const uint32_t sb = smem_u32(sm);
    const int tid = threadIdx.x, wid = tid >> 5, lane = tid & 31;
    const int wm = wid >> 2, wn = wid & 3;
    const int m0 = blockIdx.y * 128, n0 = blockIdx.x * 128;

    float acc[4][4][4];
    #pragma unroll
    for (int i = 0; i < 4; i++)
        #pragma unroll
        for (int j = 0; j < 4; j++)
            #pragma unroll
            for (int e = 0; e < 4; e++) acc[i][j][e] = 0.0f;

    #define GEMM_ISSUE(c, st) do {                                             \
        int _p = (c) >> 4; int _kb = ((c) & 15) * 64;                          \
        const __nv_bfloat16* _Ap = (_p == 1) ? Al : Ah;                        \
        const __nv_bfloat16* _Bp = (_p == 2) ? Bl : Bh;                        \
        uint32_t _da = sb + (st) * GSTG;                                       \
        uint32_t _db = sb + 3*GSTG + (st) * GSTG;                              \
        _Pragma("unroll")                                                      \
        for (int _j = 0; _j < 4; _j++) {                                       \
            int _idx = tid + _j*256;                                           \
            int _row = _idx >> 3, _q = _idx & 7;                               \
            cp16(_da + _row*GPITCH + _q*16,                                    \
                 _Ap + (size_t)(m0+_row)*DD + _kb + _q*8);                     \
            cp16(_db + _row*GPITCH + _q*16,                                    \
                 _Bp + (size_t)(n0+_row)*DD + _kb + _q*8);                     \
        }                                                                      \
    } while (0)

    GEMM_ISSUE(0, 0); CP_COMMIT();
    GEMM_ISSUE(1, 1); CP_COMMIT();

    const int NCH = 48;
    int cur = 0;
    for (int c = 0; c < NCH; c++) {
        CP_WAIT(1);
        __syncthreads();
        int nxt = cur + 2 >= 3 ? cur - 1 : cur + 2;
        if (c + 2 < NCH) GEMM_ISSUE(c + 2, nxt);
        CP_COMMIT();

        uint32_t da = sb + cur * GSTG;
        uint32_t db = sb + 3*GSTG + cur * GSTG;

        #pragma unroll
        for (int kc2 = 0; kc2 < 2; kc2++) {
            uint32_t bfr[4][4];
            #pragma unroll
            for (int nt = 0; nt < 4; nt++)
                ldsm4(bfr[nt], db + (wn*32 + nt*8 + (lane & 7))*GPITCH
                               + kc2*64 + (lane >> 3)*16);
            #pragma unroll
            for (int kk = 0; kk < 2; kk++) {
                uint32_t afr[4][4];
                #pragma unroll
                for (int mt = 0; mt < 4; mt++)
                    ldsm4(afr[mt], da + (wm*64 + mt*16 + (lane & 15))*GPITCH
                                   + kc2*64 + kk*32 + (lane >> 4)*16);
                #pragma unroll
                for (int mt = 0; mt < 4; mt++)
                    #pragma unroll
                    for (int nt = 0; nt < 4; nt++)
                        mma_bf16(acc[mt][nt], afr[mt], bfr[nt][kk*2], bfr[nt][kk*2+1]);
            }
        }
        cur = cur + 1 >= 3 ? 0 : cur + 1;
    }

    #pragma unroll
    for (int mt = 0; mt < 4; mt++) {
        #pragma unroll
        for (int rr = 0; rr < 2; rr++) {
            int row = wm*64 + mt*16 + (lane >> 2) + rr*8;
            int m = m0 + row;
            #pragma unroll
            for (int nt = 0; nt < 4; nt++) {
                int col = n0 + wn*32 + nt*8 + 2*(lane & 3);
                float v0 = acc[mt][nt][rr*2]   + bias[col];
                float v1 = acc[mt][nt][rr*2+1] + bias[col+1];
                if (mode == 1) {
                    float2 f2; f2.x = v0; f2.y = v1;
                    *(float2*)&out[(size_t)m*DD + col] = f2;
                } else {
                    int h = col / 192;
                    int t = col - h*192;
                    int which = t >> 6;
                    int hd = t & 63;
                    if (which == 0) { v0 *= QSCALE; v1 *= QSCALE; }
                    __nv_bfloat162 h2, l2;
                    split2(v0, v1, h2, l2);
                    int b = m >> 11, s = m & 2047;
                    size_t off = (((size_t)b*HH + h)*SS + s)*HD + hd;
                    __nv_bfloat16* dh = (which == 0) ? g_Qh : (which == 1) ? g_Kh : g_Vh;
                    __nv_bfloat16* dl = (which == 0) ? g_Ql : (which == 1) ? g_Kl : g_Vl;
                    *(__nv_bfloat162*)(dh + off) = h2;
                    *(__nv_bfloat162*)(dl + off) = l2;
                }
            }
        }
    }
}

// ---------------------------------------------------------------------------
// Flash attention v9: warp-local softmax (per key-half (m,l,O) state), P is
// warp-private smem (no barrier!), PV per-half over full HD=64. 1 syncthreads
// per KV tile. Cross-half merge once at the end.
// ---------------------------------------------------------------------------
#define QPITCH 272
#define VPITCH 144
#define QS_OFF 0
#define KS_OFF 17408                 // Q: 64*272
#define KBUF   17408                 // K buf: 64*272
#define VS_OFF (KS_OFF + 2*KBUF)     // 52224
#define VBUF   18432                 // V buf: 128*144
#define PS_OFF (VS_OFF + 2*VBUF)     // 89088: per-warp P, 8 x 2048B
#define RED_OFF (PS_OFF + 16384)     // 105472: m/l merge [2][64] + [2][64]
#define SMEM_ATTN (RED_OFF + 1024)   // 106496
// merge O exchange buffer reuses KS_OFF region (64 rows x 256B = 16KB)

__global__ void __launch_bounds__(256, 2) attn_kernel()
{
    const int qt = blockIdx.x;   // 0..31
    const int bh = blockIdx.y;   // 0..63
    extern __shared__ char sm[];
    const uint32_t sb = smem_u32(sm);
    const int tid = threadIdx.x, wid = tid >> 5, lane = tid & 31;
    const int wm = wid >> 1, wn = wid & 1;

    const size_t base = (size_t)bh * SS * HD;
    const __nv_bfloat16* Qh = g_Qh + base + (size_t)qt*64*HD;
    const __nv_bfloat16* Ql = g_Ql + base + (size_t)qt*64*HD;
    const __nv_bfloat16* Kh = g_Kh + base;
    const __nv_bfloat16* Kl = g_Kl + base;
    const __nv_bfloat16* Vh = g_Vh + base;
    const __nv_bfloat16* Vl = g_Vl + base;

    // ---- load Q: phys [Qh(128B) | Ql(128B)] per row ----
    #pragma unroll
    for (int j = 0; j < 4; j++) {
        int idx = tid + j*256;
        int row = idx >> 4, q = idx & 15;
        if (q < 8)
            cp16(sb + QS_OFF + row*QPITCH + q*16, Qh + (size_t)row*HD + q*8);
        else
            cp16(sb + QS_OFF + row*QPITCH + 128 + (q-8)*16, Ql + (size_t)row*HD + (q-8)*8);
    }

    #define LOAD_KV(t, buf) do {                                               \
        int _s0 = (t) * 64;                                                    \
        _Pragma("unroll")                                                      \
        for (int j = 0; j < 4; j++) {                                          \
            int _idx = tid + j*256;                                            \
            int _row = _idx >> 4, _q = _idx & 15;                              \
            if (_q < 8)                                                        \
                cp16(sb + KS_OFF + (buf)*KBUF + _row*QPITCH + _q*16,           \
                     Kh + (size_t)(_s0 + _row)*HD + _q*8);                     \
            else                                                               \
                cp16(sb + KS_OFF + (buf)*KBUF + _row*QPITCH + 128 + (_q-8)*16, \
                     Kl + (size_t)(_s0 + _row)*HD + (_q-8)*8);                 \
        }                                                                      \
        _Pragma("unroll")                                                      \
        for (int j = 0; j < 4; j++) {                                          \
            int _idx = tid + j*256;                                            \
            int _vr = _idx >> 3, _q = _idx & 7;                                \
            const __nv_bfloat16* _src = (_vr < 64)                             \
                ? Vh + (size_t)(_s0 + _vr)*HD + _q*8                           \
                : Vl + (size_t)(_s0 + _vr - 64)*HD + _q*8;                     \
            cp16(sb + VS_OFF + (buf)*VBUF + _vr*VPITCH + _q*16, _src);         \
        }                                                                      \
    } while (0)

    LOAD_KV(0, 0);
    CP_COMMIT();

    // per-half accumulators: 16 q-rows x full 64 HD per warp
    float oacc[8][4];
    #pragma unroll
    for (int j = 0; j < 8; j++)
        #pragma unroll
        for (int e = 0; e < 4; e++) oacc[j][e] = 0.0f;
    float mst[2] = {-1e30f, -1e30f};
    float lst[2] = {0.0f, 0.0f};

    const int rbase = wm*16 + (lane >> 2);
    // per-warp private P region: 16 rows x 128B ([Ph 64B | Pl 64B])
    const uint32_t psw = sb + PS_OFF + wid * 2048;

    const int qoff_tab[6] = {0, 64, 128, 192, 0, 64};     // Q: [h|l|h]
    const int koff_tab[6] = {0, 64, 0, 64, 128, 192};     // K: [h|h|l]

    for (int t = 0; t < 32; t++) {
        const int buf = t & 1;
        CP_WAIT(0);
        __syncthreads();                       // sole per-tile block barrier
        if (t + 1 < 32) LOAD_KV(t + 1, buf ^ 1);
        CP_COMMIT();

        // ---- S = Q_ext . K_ext^T : warp computes 16 q-rows x its 32 keys ----
        float sacc[4][4];
        #pragma unroll
        for (int j = 0; j < 4; j++)
            #pragma unroll
            for (int e = 0; e < 4; e++) sacc[j][e] = 0.0f;

        const uint32_t kb = sb + KS_OFF + buf*KBUF;
        #pragma unroll
        for (int kc = 0; kc < 6; kc++) {
            uint32_t bfr[4][4];
            #pragma unroll
            for (int nt = 0; nt < 4; nt++)
                ldsm4(bfr[nt], kb + (wn*32 + nt*8 + (lane & 7))*QPITCH
                               + koff_tab[kc] + (lane >> 3)*16);
            #pragma unroll
            for (int kk = 0; kk < 2; kk++) {
                uint32_t afr[4];
                ldsm4(afr, sb + QS_OFF + (wm*16 + (lane & 15))*QPITCH
                           + qoff_tab[kc] + kk*32 + (lane >> 4)*16);
                #pragma unroll
                for (int nt = 0; nt < 4; nt++)
                    mma_bf16(sacc[nt], afr, bfr[nt][kk*2], bfr[nt][kk*2+1]);
            }
        }

        // ---- warp-local online softmax over this warp's 32 keys ----
        float alpha[2];
        #pragma unroll
        for (int rr = 0; rr < 2; rr++) {
            float mx = sacc[0][rr*2];
            #pragma unroll
            for (int nt = 0; nt < 4; nt++) {
                mx = fmaxf(mx, sacc[nt][rr*2]);
                mx = fmaxf(mx, sacc[nt][rr*2+1]);
            }
            mx = fmaxf(mx, __shfl_xor_sync(0xffffffffu, mx, 1));
            mx = fmaxf(mx, __shfl_xor_sync(0xffffffffu, mx, 2));
            float mn = fmaxf(mst[rr], mx);
            alpha[rr] = ex2(mst[rr] - mn);
            mst[rr] = mn;
            float sum = 0.0f;
            #pragma unroll
            for (int nt = 0; nt < 4; nt++) {
                float p0 = ex2(sacc[nt][rr*2]   - mn);
                float p1 = ex2(sacc[nt][rr*2+1] - mn);
                sacc[nt][rr*2] = p0; sacc[nt][rr*2+1] = p1;
                sum += p0 + p1;
            }
            sum += __shfl_xor_sync(0xffffffffu, sum, 1);
            sum += __shfl_xor_sync(0xffffffffu, sum, 2);
            lst[rr] = lst[rr]*alpha[rr] + sum;
            #pragma unroll
            for (int j = 0; j < 8; j++) {
                oacc[j][rr*2]   *= alpha[rr];
                oacc[j][rr*2+1] *= alpha[rr];
            }
        }

        // ---- write warp-private P [Ph(64B) | Pl(64B)] per row ----
        #pragma unroll
        for (int rr = 0; rr < 2; rr++) {
            int rl = (lane >> 2) + rr*8;
            uint32_t prow = psw + rl*128;
            #pragma unroll
            for (int nt = 0; nt < 4; nt++) {
                int kl = nt*8 + 2*(lane & 3);
                __nv_bfloat162 h2, l2;
                split2(sacc[nt][rr*2], sacc[nt][rr*2+1], h2, l2);
                *(__nv_bfloat162*)(sm + (prow - sb) + kl*2)      = h2;
                *(__nv_bfloat162*)(sm + (prow - sb) + 64 + kl*2) = l2;
            }
        }
        __syncwarp();

        // ---- O += P_ext . V_ext over this warp's keys (ext-K 96), HD 64 ----
        // steps: Ph.Vh (0,1) | Pl.Vh (2,3) | Ph.Vl (4,5)
        const uint32_t vb = sb + VS_OFF + buf*VBUF;
        const int poff_tab[6] = {0, 32, 64, 96, 0, 32};
        #pragma unroll
        for (int s = 0; s < 6; s++) {
            int vrow = (s < 2) ? wn*32 + s*16
                     : (s < 4) ? wn*32 + (s-2)*16
                               : 64 + wn*32 + (s-4)*16;
            uint32_t afr[4];
            ldsm4(afr, psw + (lane & 15)*128 + poff_tab[s] + (lane >> 4)*16);
            uint32_t bfr[4][4];
            #pragma unroll
            for (int ng = 0; ng < 4; ng++)
                ldsm4t(bfr[ng], vb + (vrow + (lane & 7) + ((lane >> 3) & 1)*8)*VPITCH
                                + (ng*16 + (lane >> 4)*8)*2);
            #pragma unroll
            for (int nt = 0; nt < 8; nt++) {
                int ng = nt >> 1, nh = nt & 1;
                mma_bf16(oacc[nt], afr, bfr[ng][nh*2], bfr[ng][nh*2+1]);
            }
        }
        __syncwarp();   // P reuse next tile (warp-private)
    }

    // ---- cross-half merge ----
    float* mm = (float*)(sm + RED_OFF);   // [2][64]
    float* ll = mm + 128;                 // [2][64]
    #pragma unroll
    for (int rr = 0; rr < 2; rr++) {
        if ((lane & 3) == 0) {
            mm[wn*64 + rbase + rr*8] = mst[rr];
            ll[wn*64 + rbase + rr*8] = lst[rr];
        }
    }
    __syncthreads();   // also: all warps done with all tiles

    float aw[2], linv[2];
    #pragma unroll
    for (int rr = 0; rr < 2; rr++) {
        int row = rbase + rr*8;
        float m = fmaxf(mm[row], mm[64 + row]);
        float a0 = ex2(mm[row] - m), a1 = ex2(mm[64 + row] - m);
        float ltot = ll[row]*a0 + ll[64 + row]*a1;
        aw[rr] = ex2(mst[rr] - m);
        linv[rr] = 1.0f / ltot;
    }

    float* oex = (float*)(sm + KS_OFF);   // 64 rows x 64 floats (256B pitch)
    if (wn == 1) {
        #pragma unroll
        for (int rr = 0; rr < 2; rr++) {
            int row = rbase + rr*8;
            #pragma unroll
            for (int nt = 0; nt < 8; nt++) {
                int col = nt*8 + 2*(lane & 3);
                float2 f2;
                f2.x = oacc[nt][rr*2]   * aw[rr];
                f2.y = oacc[nt][rr*2+1] * aw[rr];
                *(float2*)&oex[row*64 + col] = f2;
            }
        }
    }
    __syncthreads();
    if (wn == 0) {
        #pragma unroll
        for (int rr = 0; rr < 2; rr++) {
            int row = rbase + rr*8;
            size_t off0 = base + (size_t)(qt*64 + row)*HD;
            #pragma unroll
            for (int nt = 0; nt < 8; nt++) {
                int col = nt*8 + 2*(lane & 3);
                float2 o1 = *(float2*)&oex[row*64 + col];
                float v0 = (oacc[nt][rr*2]   * aw[rr] + o1.x) * linv[rr];
                float v1 = (oacc[nt][rr*2+1] * aw[rr] + o1.y) * linv[rr];
                __nv_bfloat162 h2, l2;
                split2(v0, v1, h2, l2);
                *(__nv_bfloat162*)(g_Oh + off0 + col) = h2;
                *(__nv_bfloat162*)(g_Ol + off0 + col) = l2;
            }
        }
    }
}

// ---------------------------------------------------------------------------
extern "C" void kernel_launch(void* const* d_in, const int* in_sizes, int n_in,
                              void* d_out, int out_size)
{
    const float* x    = (const float*)d_in[0];
    const float* Wqkv = (const float*)d_in[1];
    const float* bqkv = (const float*)d_in[2];
    const float* Wo   = (const float*)d_in[3];
    const float* bo   = (const float*)d_in[4];
    float* out = (float*)d_out;

    cudaFuncSetAttribute(gemm_ext_kernel,
                         cudaFuncAttributeMaxDynamicSharedMemorySize, SMEM_GEMM);
    cudaFuncSetAttribute(attn_kernel,
                         cudaFuncAttributeMaxDynamicSharedMemorySize, SMEM_ATTN);

    __nv_bfloat16 *Xh, *Xl, *WqTh, *WqTl, *WoTh, *WoTl, *Oh, *Ol;
    cudaGetSymbolAddress((void**)&Xh,   g_Xh);
    cudaGetSymbolAddress((void**)&Xl,   g_Xl);
    cudaGetSymbolAddress((void**)&WqTh, g_WqTh);
    cudaGetSymbolAddress((void**)&WqTl, g_WqTl);
    cudaGetSymbolAddress((void**)&WoTh, g_WoTh);
    cudaGetSymbolAddress((void**)&WoTl, g_WoTl);
    cudaGetSymbolAddress((void**)&Oh,   g_Oh);
    cudaGetSymbolAddress((void**)&Ol,   g_Ol);

    prep_kernel<<<8192 + 3072 + 1024, 256>>>(x, Wqkv, Wo);

    gemm_ext_kernel<<<dim3(NQKV/128, MTOT/128), 256, SMEM_GEMM>>>(
        Xh, Xl, WqTh, WqTl, bqkv, nullptr, 0);

    attn_kernel<<<dim3(SS/64, NHEADS), 256, SMEM_ATTN>>>();

    gemm_ext_kernel<<<dim3(DD/128, MTOT/128), 256, SMEM_GEMM>>>(
        Oh, Ol, WoTh, WoTl, bo, out, 1);
}

// round 10
// speedup vs baseline: 1.2140x; 1.2140x over previous
#include <cuda_runtime.h>
#include <cuda_bf16.h>
#include <cstdint>
#include <math.h>

// Problem constants
#define BB 4
#define SS 2048
#define DD 1024
#define HH 16
#define HD 64
#define MTOT (BB*SS)      // 8192
#define NQKV (3*DD)       // 3072
#define NHEADS (BB*HH)    // 64

// Q pre-scale: 1/sqrt(64) * log2(e)  (softmax done in exp2 domain)
#define QSCALE 0.1803368801111204f

// ---------------------------------------------------------------------------
// Scratch (static device globals — allowed)
// ---------------------------------------------------------------------------
__device__ __nv_bfloat16 g_Xh[(size_t)MTOT*DD];
__device__ __nv_bfloat16 g_Xl[(size_t)MTOT*DD];
__device__ __nv_bfloat16 g_WqTh[(size_t)NQKV*DD];
__device__ __nv_bfloat16 g_WqTl[(size_t)NQKV*DD];
__device__ __nv_bfloat16 g_WoTh[(size_t)DD*DD];
__device__ __nv_bfloat16 g_WoTl[(size_t)DD*DD];
__device__ __nv_bfloat16 g_Qh[(size_t)NHEADS*SS*HD];
__device__ __nv_bfloat16 g_Ql[(size_t)NHEADS*SS*HD];
__device__ __nv_bfloat16 g_Kh[(size_t)NHEADS*SS*HD];
__device__ __nv_bfloat16 g_Kl[(size_t)NHEADS*SS*HD];
__device__ __nv_bfloat16 g_Vh[(size_t)NHEADS*SS*HD];
__device__ __nv_bfloat16 g_Vl[(size_t)NHEADS*SS*HD];
__device__ __nv_bfloat16 g_Oh[(size_t)MTOT*DD];
__device__ __nv_bfloat16 g_Ol[(size_t)MTOT*DD];

// ---------------------------------------------------------------------------
// PTX helpers (plain compute_103-compatible: mma.sync / ldmatrix / cp.async)
// ---------------------------------------------------------------------------
__device__ __forceinline__ uint32_t smem_u32(const void* p) {
    uint32_t a;
    asm("{ .reg .u64 t; cvta.to.shared.u64 t, %1; cvt.u32.u64 %0, t; }"
        : "=r"(a) : "l"(p));
    return a;
}
__device__ __forceinline__ void cp16(uint32_t dst, const void* src) {
    asm volatile("cp.async.cg.shared.global [%0], [%1], 16;\n"
                 :: "r"(dst), "l"(src));
}
#define CP_COMMIT() asm volatile("cp.async.commit_group;\n" ::: "memory")
#define CP_WAIT(n)  asm volatile("cp.async.wait_group %0;\n" :: "n"(n) : "memory")

__device__ __forceinline__ void ldsm4(uint32_t* r, uint32_t addr) {
    asm volatile("ldmatrix.sync.aligned.m8n8.x4.shared.b16 {%0,%1,%2,%3}, [%4];\n"
                 : "=r"(r[0]), "=r"(r[1]), "=r"(r[2]), "=r"(r[3]) : "r"(addr));
}
__device__ __forceinline__ void ldsm4t(uint32_t* r, uint32_t addr) {
    asm volatile("ldmatrix.sync.aligned.m8n8.x4.trans.shared.b16 {%0,%1,%2,%3}, [%4];\n"
                 : "=r"(r[0]), "=r"(r[1]), "=r"(r[2]), "=r"(r[3]) : "r"(addr));
}
__device__ __forceinline__ void mma_bf16(float* c, const uint32_t* a,
                                         uint32_t b0, uint32_t b1) {
    asm volatile(
        "mma.sync.aligned.m16n8k16.row.col.f32.bf16.bf16.f32 "
        "{%0,%1,%2,%3}, {%4,%5,%6,%7}, {%8,%9}, {%0,%1,%2,%3};\n"
        : "+f"(c[0]), "+f"(c[1]), "+f"(c[2]), "+f"(c[3])
        : "r"(a[0]), "r"(a[1]), "r"(a[2]), "r"(a[3]), "r"(b0), "r"(b1));
}
__device__ __forceinline__ float ex2(float x) {
    float y;
    asm("ex2.approx.ftz.f32 %0, %1;" : "=f"(y) : "f"(x));
    return y;
}
__device__ __forceinline__ void split2(float x, float y,
                                       __nv_bfloat162& h2, __nv_bfloat162& l2) {
    __nv_bfloat16 hx = __float2bfloat16(x);
    __nv_bfloat16 hy = __float2bfloat16(y);
    h2.x = hx; h2.y = hy;
    l2.x = __float2bfloat16(x - __bfloat162float(hx));
    l2.y = __float2bfloat16(y - __bfloat162float(hy));
}

// ---------------------------------------------------------------------------
// Fused prep: one launch.
//   blocks [0, 8192)              : split x -> g_Xh/g_Xl
//   blocks [8192, 8192+3072)      : transpose+split Wqkv -> g_WqT{h,l}
//   blocks [8192+3072, +1024)     : transpose+split Wo   -> g_WoT{h,l}
// ---------------------------------------------------------------------------
__device__ __forceinline__ void do_transpose_split(
    const float* __restrict__ W, int K, int N, int bx, int by, int tid,
    __nv_bfloat16* __restrict__ Th, __nv_bfloat16* __restrict__ Tl)
{
    __shared__ float t[32][33];
    int nb = bx * 32, kb = by * 32;
    int tx = tid & 31, ty = tid >> 5;
    #pragma unroll
    for (int j = 0; j < 4; j++)
        t[ty + j*8][tx] = W[(size_t)(kb + ty + j*8) * N + nb + tx];
    __syncthreads();
    #pragma unroll
    for (int j = 0; j < 4; j++) {
        int n = nb + ty + j*8;
        float v = t[tx][ty + j*8];
        __nv_bfloat16 h = __float2bfloat16(v);
        Th[(size_t)n * K + kb + tx] = h;
        Tl[(size_t)n * K + kb + tx] = __float2bfloat16(v - __bfloat162float(h));
    }
}

__global__ void __launch_bounds__(256) prep_kernel(
    const float* __restrict__ x, const float* __restrict__ Wqkv,
    const float* __restrict__ Wo)
{
    int bid = blockIdx.x;
    int tid = threadIdx.x;
    if (bid < 8192) {
        size_t i4 = ((size_t)bid * 256 + tid) * 4;
        float4 v = *(const float4*)(x + i4);
        __nv_bfloat162 h0, l0, h1, l1;
        split2(v.x, v.y, h0, l0);
        split2(v.z, v.w, h1, l1);
        *(__nv_bfloat162*)(g_Xh + i4)     = h0;
        *(__nv_bfloat162*)(g_Xh + i4 + 2) = h1;
        *(__nv_bfloat162*)(g_Xl + i4)     = l0;
        *(__nv_bfloat162*)(g_Xl + i4 + 2) = l1;
    } else if (bid < 8192 + 3072) {
        int b = bid - 8192;                 // 96 x 32 grid (nb x kb)
        do_transpose_split(Wqkv, DD, NQKV, b % 96, b / 96, tid, g_WqTh, g_WqTl);
    } else {
        int b = bid - 8192 - 3072;          // 32 x 32 grid
        do_transpose_split(Wo, DD, DD, b % 32, b / 32, tid, g_WoTh, g_WoTl);
    }
}

// ---------------------------------------------------------------------------
// Extended-K bf16 GEMM (3-pass split as K=3072):
//   C[M][N] = sum_p  Ap . Bp^T   with A pattern [h|l|h], B pattern [h|h|l]
// BM=BN=128, BK=64 per stage, 256 threads, 8 warps (2m x 4n),
// 3-stage cp.async (110.6KB smem), 2 CTAs/SM.  (R6 best variant)
// ---------------------------------------------------------------------------
#define GPITCH 144
#define GSTG (128*GPITCH)   // 18432 per operand per stage
#define SMEM_GEMM (6*GSTG)  // 110592

__global__ void __launch_bounds__(256, 2) gemm_ext_kernel(
    const __nv_bfloat16* __restrict__ Ah, const __nv_bfloat16* __restrict__ Al,
    const __nv_bfloat16* __restrict__ Bh, const __nv_bfloat16* __restrict__ Bl,
    const float* __restrict__ bias, float* __restrict__ out, int mode)
{
    extern __shared__ char sm[];
    const uint32_t sb = smem_u32(sm);
    const int tid = threadIdx.x, wid = tid >> 5, lane = tid & 31;
    const int wm = wid >> 2, wn = wid & 3;
    const int m0 = blockIdx.y * 128, n0 = blockIdx.x * 128;

    float acc[4][4][4];
    #pragma unroll
    for (int i = 0; i < 4; i++)
        #pragma unroll
        for (int j = 0; j < 4; j++)
            #pragma unroll
            for (int e = 0; e < 4; e++) acc[i][j][e] = 0.0f;

    #define GEMM_ISSUE(c, st) do {                                             \
        int _p = (c) >> 4; int _kb = ((c) & 15) * 64;                          \
        const __nv_bfloat16* _Ap = (_p == 1) ? Al : Ah;                        \
        const __nv_bfloat16* _Bp = (_p == 2) ? Bl : Bh;                        \
        uint32_t _da = sb + (st) * GSTG;                                       \
        uint32_t _db = sb + 3*GSTG + (st) * GSTG;                              \
        _Pragma("unroll")                                                      \
        for (int _j = 0; _j < 4; _j++) {                                       \
            int _idx = tid + _j*256;                                           \
            int _row = _idx >> 3, _q = _idx & 7;                               \
            cp16(_da + _row*GPITCH + _q*16,                                    \
                 _Ap + (size_t)(m0+_row)*DD + _kb + _q*8);                     \
            cp16(_db + _row*GPITCH + _q*16,                                    \
                 _Bp + (size_t)(n0+_row)*DD + _kb + _q*8);                     \
        }                                                                      \
    } while (0)

    GEMM_ISSUE(0, 0); CP_COMMIT();
    GEMM_ISSUE(1, 1); CP_COMMIT();

    const int NCH = 48;
    int cur = 0;
    for (int c = 0; c < NCH; c++) {
        CP_WAIT(1);
        __syncthreads();
        int nxt = cur + 2 >= 3 ? cur - 1 : cur + 2;
        if (c + 2 < NCH) GEMM_ISSUE(c + 2, nxt);
        CP_COMMIT();

        uint32_t da = sb + cur * GSTG;
        uint32_t db = sb + 3*GSTG + cur * GSTG;

        #pragma unroll
        for (int kc2 = 0; kc2 < 2; kc2++) {
            uint32_t bfr[4][4];
            #pragma unroll
            for (int nt = 0; nt < 4; nt++)
                ldsm4(bfr[nt], db + (wn*32 + nt*8 + (lane & 7))*GPITCH
                               + kc2*64 + (lane >> 3)*16);
            #pragma unroll
            for (int kk = 0; kk < 2; kk++) {
                uint32_t afr[4][4];
                #pragma unroll
                for (int mt = 0; mt < 4; mt++)
                    ldsm4(afr[mt], da + (wm*64 + mt*16 + (lane & 15))*GPITCH
                                   + kc2*64 + kk*32 + (lane >> 4)*16);
                #pragma unroll
                for (int mt = 0; mt < 4; mt++)
                    #pragma unroll
                    for (int nt = 0; nt < 4; nt++)
                        mma_bf16(acc[mt][nt], afr[mt], bfr[nt][kk*2], bfr[nt][kk*2+1]);
            }
        }
        cur = cur + 1 >= 3 ? 0 : cur + 1;
    }

    #pragma unroll
    for (int mt = 0; mt < 4; mt++) {
        #pragma unroll
        for (int rr = 0; rr < 2; rr++) {
            int row = wm*64 + mt*16 + (lane >> 2) + rr*8;
            int m = m0 + row;
            #pragma unroll
            for (int nt = 0; nt < 4; nt++) {
                int col = n0 + wn*32 + nt*8 + 2*(lane & 3);
                float v0 = acc[mt][nt][rr*2]   + bias[col];
                float v1 = acc[mt][nt][rr*2+1] + bias[col+1];
                if (mode == 1) {
                    float2 f2; f2.x = v0; f2.y = v1;
                    *(float2*)&out[(size_t)m*DD + col] = f2;
                } else {
                    int h = col / 192;
                    int t = col - h*192;
                    int which = t >> 6;
                    int hd = t & 63;
                    if (which == 0) { v0 *= QSCALE; v1 *= QSCALE; }
                    __nv_bfloat162 h2, l2;
                    split2(v0, v1, h2, l2);
                    int b = m >> 11, s = m & 2047;
                    size_t off = (((size_t)b*HH + h)*SS + s)*HD + hd;
                    __nv_bfloat16* dh = (which == 0) ? g_Qh : (which == 1) ? g_Kh : g_Vh;
                    __nv_bfloat16* dl = (which == 0) ? g_Ql : (which == 1) ? g_Kl : g_Vl;
                    *(__nv_bfloat162*)(dh + off) = h2;
                    *(__nv_bfloat162*)(dl + off) = l2;
                }
            }
        }
    }
}

// ---------------------------------------------------------------------------
// Flash attention via mma.sync, 3-pass split, physical hi/lo dedup — R6/R8
// proven version (shared V fragments, cross-warp softmax, 3 barriers/tile).
// Q tile 64 rows, KV tile 64 keys. 8 warps: wm=wid>>1 (16 q-rows), wn=wid&1.
// ---------------------------------------------------------------------------
#define QPITCH 272
#define VPITCH 144
#define QS_OFF 0
#define KS_OFF 17408                 // Q: 64*272
#define KBUF   17408                 // K buf: 64*272
#define VS_OFF (KS_OFF + 2*KBUF)     // 52224
#define VBUF   18432                 // V buf: 128*144
#define PS_OFF (VS_OFF + 2*VBUF)     // 89088
#define RED_OFF (PS_OFF + 17408)     // 106496
#define SMEM_ATTN (RED_OFF + 1024)   // 107520

__global__ void __launch_bounds__(256, 2) attn_kernel()
{
    const int qt = blockIdx.x;   // 0..31
    const int bh = blockIdx.y;   // 0..63
    extern __shared__ char sm[];
    const uint32_t sb = smem_u32(sm);
    const int tid = threadIdx.x, wid = tid >> 5, lane = tid & 31;
    const int wm = wid >> 1, wn = wid & 1;

    const size_t base = (size_t)bh * SS * HD;
    const __nv_bfloat16* Qh = g_Qh + base + (size_t)qt*64*HD;
    const __nv_bfloat16* Ql = g_Ql + base + (size_t)qt*64*HD;
    const __nv_bfloat16* Kh = g_Kh + base;
    const __nv_bfloat16* Kl = g_Kl + base;
    const __nv_bfloat16* Vh = g_Vh + base;
    const __nv_bfloat16* Vl = g_Vl + base;

    // ---- load Q: phys [Qh(128B) | Ql(128B)] per row ----
    #pragma unroll
    for (int j = 0; j < 4; j++) {
        int idx = tid + j*256;
        int row = idx >> 4, q = idx & 15;
        if (q < 8)
            cp16(sb + QS_OFF + row*QPITCH + q*16, Qh + (size_t)row*HD + q*8);
        else
            cp16(sb + QS_OFF + row*QPITCH + 128 + (q-8)*16, Ql + (size_t)row*HD + (q-8)*8);
    }

    #define LOAD_KV(t, buf) do {                                               \
        int _s0 = (t) * 64;                                                    \
        _Pragma("unroll")                                                      \
        for (int j = 0; j < 4; j++) {                                          \
            int _idx = tid + j*256;                                            \
            int _row = _idx >> 4, _q = _idx & 15;                              \
            if (_q < 8)                                                        \
                cp16(sb + KS_OFF + (buf)*KBUF + _row*QPITCH + _q*16,           \
                     Kh + (size_t)(_s0 + _row)*HD + _q*8);                     \
            else                                                               \
                cp16(sb + KS_OFF + (buf)*KBUF + _row*QPITCH + 128 + (_q-8)*16, \
                     Kl + (size_t)(_s0 + _row)*HD + (_q-8)*8);                 \
        }                                                                      \
        _Pragma("unroll")                                                      \
        for (int j = 0; j < 4; j++) {                                          \
            int _idx = tid + j*256;                                            \
            int _vr = _idx >> 3, _q = _idx & 7;                                \
            const __nv_bfloat16* _src = (_vr < 64)                             \
                ? Vh + (size_t)(_s0 + _vr)*HD + _q*8                           \
                : Vl + (size_t)(_s0 + _vr - 64)*HD + _q*8;                     \
            cp16(sb + VS_OFF + (buf)*VBUF + _vr*VPITCH + _q*16, _src);         \
        }                                                                      \
    } while (0)

    LOAD_KV(0, 0);
    CP_COMMIT();

    float oacc[4][4];
    #pragma unroll
    for (int j = 0; j < 4; j++)
        #pragma unroll
        for (int e = 0; e < 4; e++) oacc[j][e] = 0.0f;
    float mst[2] = {-1e30f, -1e30f};
    float lst[2] = {0.0f, 0.0f};

    float* redm = (float*)(sm + RED_OFF);   // [2][64]
    float* reds = redm + 128;               // [2][64]
    const int rbase = wm*16 + (lane >> 2);

    const int qoff_tab[6] = {0, 64, 128, 192, 0, 64};     // Q: [h|l|h]
    const int koff_tab[6] = {0, 64, 0, 64, 128, 192};     // K: [h|h|l]

    for (int t = 0; t < 32; t++) {
        const int buf = t & 1;
        CP_WAIT(0);                            // tile t fully arrived
        __syncthreads();                       // + all warps past PV(t-1)
        if (t + 1 < 32) LOAD_KV(t + 1, buf ^ 1);
        CP_COMMIT();

        // ---- S = Q_ext . K_ext^T (64 x 64, ext K = 192) ----
        float sacc[4][4];
        #pragma unroll
        for (int j = 0; j < 4; j++)
            #pragma unroll
            for (int e = 0; e < 4; e++) sacc[j][e] = 0.0f;

        const uint32_t kb = sb + KS_OFF + buf*KBUF;
        #pragma unroll
        for (int kc = 0; kc < 6; kc++) {
            uint32_t bfr[4][4];
            #pragma unroll
            for (int nt = 0; nt < 4; nt++)
                ldsm4(bfr[nt], kb + (wn*32 + nt*8 + (lane & 7))*QPITCH
                               + koff_tab[kc] + (lane >> 3)*16);
            #pragma unroll
            for (int kk = 0; kk < 2; kk++) {
                uint32_t afr[4];
                ldsm4(afr, sb + QS_OFF + (wm*16 + (lane & 15))*QPITCH
                           + qoff_tab[kc] + kk*32 + (lane >> 4)*16);
                #pragma unroll
                for (int nt = 0; nt < 4; nt++)
                    mma_bf16(sacc[nt], afr, bfr[nt][kk*2], bfr[nt][kk*2+1]);
            }
        }

        // ---- online softmax (exp2 domain) ----
        #pragma unroll
        for (int rr = 0; rr < 2; rr++) {
            float mx = sacc[0][rr*2];
            #pragma unroll
            for (int nt = 0; nt < 4; nt++) {
                mx = fmaxf(mx, sacc[nt][rr*2]);
                mx = fmaxf(mx, sacc[nt][rr*2+1]);
            }
            mx = fmaxf(mx, __shfl_xor_sync(0xffffffffu, mx, 1));
            mx = fmaxf(mx, __shfl_xor_sync(0xffffffffu, mx, 2));
            if ((lane & 3) == 0)
                redm[wn*64 + rbase + rr*8] = mx;
        }
        __syncthreads();

        float alpha[2];
        #pragma unroll
        for (int rr = 0; rr < 2; rr++) {
            int row = rbase + rr*8;
            float rm = fmaxf(redm[row], redm[64 + row]);
            float mn = fmaxf(mst[rr], rm);
            alpha[rr] = ex2(mst[rr] - mn);
            mst[rr] = mn;
            float sum = 0.0f;
            #pragma unroll
            for (int nt = 0; nt < 4; nt++) {
                float p0 = ex2(sacc[nt][rr*2]   - mn);
                float p1 = ex2(sacc[nt][rr*2+1] - mn);
                sacc[nt][rr*2] = p0; sacc[nt][rr*2+1] = p1;
                sum += p0 + p1;
            }
            sum += __shfl_xor_sync(0xffffffffu, sum, 1);
            sum += __shfl_xor_sync(0xffffffffu, sum, 2);
            if ((lane & 3) == 0)
                reds[wn*64 + row] = sum;
        }

        // write P phys [Ph(128B) | Pl(128B)]
        #pragma unroll
        for (int rr = 0; rr < 2; rr++) {
            int row = rbase + rr*8;
            char* prow = sm + PS_OFF + row*QPITCH;
            #pragma unroll
            for (int nt = 0; nt < 4; nt++) {
                int klc = wn*32 + nt*8 + 2*(lane & 3);
                __nv_bfloat162 h2, l2;
                split2(sacc[nt][rr*2], sacc[nt][rr*2+1], h2, l2);
                *(__nv_bfloat162*)(prow + klc*2)       = h2;
                *(__nv_bfloat162*)(prow + 128 + klc*2) = l2;
            }
        }
        __syncthreads();

        // l update + O rescale
        #pragma unroll
        for (int rr = 0; rr < 2; rr++) {
            int row = rbase + rr*8;
            lst[rr] = lst[rr]*alpha[rr] + reds[row] + reds[64+row];
            #pragma unroll
            for (int nt = 0; nt < 4; nt++) {
                oacc[nt][rr*2]   *= alpha[rr];
                oacc[nt][rr*2+1] *= alpha[rr];
            }
        }

        // ---- O += P_ext . V_ext (ext K = 192 over keys) ----
        const uint32_t vb = sb + VS_OFF + buf*VBUF;
        #pragma unroll
        for (int k16 = 0; k16 < 12; k16++) {
            int poff  = (k16 < 4) ? k16*32 : (k16 < 8) ? 128 + (k16-4)*32 : (k16-8)*32;
            int vbase = (k16 < 4) ? k16*16 : (k16 < 8) ? (k16-4)*16 : 64 + (k16-8)*16;
            uint32_t afr[4];
            ldsm4(afr, sb + PS_OFF + (wm*16 + (lane & 15))*QPITCH
                       + poff + (lane >> 4)*16);
            uint32_t bfr[2][4];
            #pragma unroll
            for (int ng = 0; ng < 2; ng++)
                ldsm4t(bfr[ng], vb + (vbase + (lane & 7) + ((lane >> 3) & 1)*8)*VPITCH
                                + (wn*32 + ng*16 + (lane >> 4)*8)*2);
            #pragma unroll
            for (int nt = 0; nt < 4; nt++) {
                int ng = nt >> 1, nh = nt & 1;
                mma_bf16(oacc[nt], afr, bfr[ng][nh*2], bfr[ng][nh*2+1]);
            }
        }
    }

    // ---- finalize: O/l, split, store ----
    #pragma unroll
    for (int rr = 0; rr < 2; rr++) {
        float inv = 1.0f / lst[rr];
        int row = rbase + rr*8;
        size_t off0 = base + (size_t)(qt*64 + row)*HD;
        #pragma unroll
        for (int nt = 0; nt < 4; nt++) {
            int hd = wn*32 + nt*8 + 2*(lane & 3);
            __nv_bfloat162 h2, l2;
            split2(oacc[nt][rr*2]*inv, oacc[nt][rr*2+1]*inv, h2, l2);
            *(__nv_bfloat162*)(g_Oh + off0 + hd) = h2;
            *(__nv_bfloat162*)(g_Ol + off0 + hd) = l2;
        }
    }
}

// ---------------------------------------------------------------------------
extern "C" void kernel_launch(void* const* d_in, const int* in_sizes, int n_in,
                              void* d_out, int out_size)
{
    const float* x    = (const float*)d_in[0];
    const float* Wqkv = (const float*)d_in[1];
    const float* bqkv = (const float*)d_in[2];
    const float* Wo   = (const float*)d_in[3];
    const float* bo   = (const float*)d_in[4];
    float* out = (float*)d_out;

    cudaFuncSetAttribute(gemm_ext_kernel,
                         cudaFuncAttributeMaxDynamicSharedMemorySize, SMEM_GEMM);
    cudaFuncSetAttribute(attn_kernel,
                         cudaFuncAttributeMaxDynamicSharedMemorySize, SMEM_ATTN);

    __nv_bfloat16 *Xh, *Xl, *WqTh, *WqTl, *WoTh, *WoTl, *Oh, *Ol;
    cudaGetSymbolAddress((void**)&Xh,   g_Xh);
    cudaGetSymbolAddress((void**)&Xl,   g_Xl);
    cudaGetSymbolAddress((void**)&WqTh, g_WqTh);
    cudaGetSymbolAddress((void**)&WqTl, g_WqTl);
    cudaGetSymbolAddress((void**)&WoTh, g_WoTh);
    cudaGetSymbolAddress((void**)&WoTl, g_WoTl);
    cudaGetSymbolAddress((void**)&Oh,   g_Oh);
    cudaGetSymbolAddress((void**)&Ol,   g_Ol);

    prep_kernel<<<8192 + 3072 + 1024, 256>>>(x, Wqkv, Wo);

    gemm_ext_kernel<<<dim3(NQKV/128, MTOT/128), 256, SMEM_GEMM>>>(
        Xh, Xl, WqTh, WqTl, bqkv, nullptr, 0);

    attn_kernel<<<dim3(SS/64, NHEADS), 256, SMEM_ATTN>>>();

    gemm_ext_kernel<<<dim3(DD/128, MTOT/128), 256, SMEM_GEMM>>>(
        Oh, Ol, WoTh, WoTl, bo, out, 1);
}